// round 10
// baseline (speedup 1.0000x reference)
#include <cuda_runtime.h>
#include <cuda_bf16.h>
#include <cuda_fp16.h>
#include <math.h>

#define Bq   4
#define Lq   1024
#define Dq   768
#define Hq   12
#define BSq  64
#define Mq   48
#define NEq  24
#define Pq   552
#define Eq   576
#define Rq   97
#define NPq  2208

typedef __nv_bfloat16 bf16;

// ---------------- scratch ----------------
__device__ float g_cur    [Bq*Hq*NEq*Lq];
__device__ float g_ci     [NPq*Dq];
__device__ float g_bh     [NPq*Dq];
__device__ float g_bt     [NPq*Dq];
__device__ int   g_mask   [NPq];
__device__ float g_Ni     [Bq*NEq*Dq];
__device__ float g_Nj     [Bq*NEq*Dq];
__device__ float g_Hs     [Bq*NEq*Dq];
__device__ float g_EfW    [NPq*Dq];
__device__ float g_f      [Bq*Eq*Dq];
__device__ float g_score  [Bq*Eq*Hq];
__device__ float g_alpha  [Bq*Eq*Hq];
__device__ float g_relpart[(size_t)24*NPq*128];
__device__ int   g_inc    [NEq*23];
__device__ float g_Ebh[96*Dq], g_Ebt[96*Dq], g_Erh[96*Dq], g_Ert[96*Dq];

// bf16 (mask-critical chain)
__device__ bf16 g_enth[Bq*NEq*Dq],   g_entl[Bq*NEq*Dq];
__device__ bf16 g_cah [Bq*Pq*Lq],    g_cal [Bq*Pq*Lq];
__device__ bf16 g_cih [NPq*Dq],      g_cil [NPq*Dq];
__device__ bf16 g_ctxh[Bq*Lq*Dq],    g_ctxl[Bq*Lq*Dq];
__device__ bf16 g_Whbh[2*Dq*Dq],     g_Whbl[2*Dq*Dq];
__device__ bf16 g_Wtbh[2*Dq*Dq],     g_Wtbl[2*Dq*Dq];
// fp16 (post-mask chain)
__device__ __half g_cif16 [NPq*Dq];
__device__ __half g_entf16[Bq*NEq*Dq];
__device__ __half g_nchf16[NPq*Dq];
__device__ __half g_noutf16[Bq*NEq*Dq];
__device__ __half g_Whh [2*Dq*Dq],   g_Whl [2*Dq*Dq];
__device__ __half g_Wth [2*Dq*Dq],   g_Wtl [2*Dq*Dq];
__device__ __half g_Wfijh[Dq*Dq],    g_Wfijl[Dq*Dq];
__device__ __half g_Wnih[Dq*Dq],     g_Wnil[Dq*Dq];
__device__ __half g_Wnjh[Dq*Dq],     g_Wnjl[Dq*Dq];
__device__ __half g_Wnodeh[Dq*Dq],   g_Wnodel[Dq*Dq];
__device__ __half g_Wpadh[(size_t)Hq*4096*128], g_Wpadl[(size_t)Hq*4096*128];

// ---------------- helpers ----------------
__device__ __forceinline__ void split2(float x, bf16& h, bf16& l) {
    h = __float2bfloat16(x);
    l = __float2bfloat16(x - __bfloat162float(h));
}
__device__ __forceinline__ void split2h(float x, __half& h, __half& l) {
    h = __float2half(x);
    l = __float2half(x - __half2float(h));
}
__device__ __forceinline__ unsigned su32(const void* p) {
    return (unsigned)__cvta_generic_to_shared(p);
}
__device__ __forceinline__ void ldmx4(unsigned* r, unsigned a) {
    asm volatile("ldmatrix.sync.aligned.m8n8.x4.shared.b16 {%0,%1,%2,%3}, [%4];"
        : "=r"(r[0]), "=r"(r[1]), "=r"(r[2]), "=r"(r[3]) : "r"(a));
}
__device__ __forceinline__ void ldmx4t(unsigned* r, unsigned a) {
    asm volatile("ldmatrix.sync.aligned.m8n8.x4.trans.shared.b16 {%0,%1,%2,%3}, [%4];"
        : "=r"(r[0]), "=r"(r[1]), "=r"(r[2]), "=r"(r[3]) : "r"(a));
}
__device__ __forceinline__ void mma16816(float* c, const unsigned* a, const unsigned* b) {
    asm volatile("mma.sync.aligned.m16n8k16.row.col.f32.bf16.bf16.f32 "
        "{%0,%1,%2,%3}, {%4,%5,%6,%7}, {%8,%9}, {%0,%1,%2,%3};"
        : "+f"(c[0]), "+f"(c[1]), "+f"(c[2]), "+f"(c[3])
        : "r"(a[0]), "r"(a[1]), "r"(a[2]), "r"(a[3]), "r"(b[0]), "r"(b[1]));
}
__device__ __forceinline__ void mma16816f(float* c, const unsigned* a, const unsigned* b) {
    asm volatile("mma.sync.aligned.m16n8k16.row.col.f32.f16.f16.f32 "
        "{%0,%1,%2,%3}, {%4,%5,%6,%7}, {%8,%9}, {%0,%1,%2,%3};"
        : "+f"(c[0]), "+f"(c[1]), "+f"(c[2]), "+f"(c[3])
        : "r"(a[0]), "r"(a[1]), "r"(a[2]), "r"(a[3]), "r"(b[0]), "r"(b[1]));
}
__device__ __forceinline__ uint4 pack8h(const __half* x) {
    uint4 u;
    u.x = ((unsigned)__half_as_ushort(x[1]) << 16) | __half_as_ushort(x[0]);
    u.y = ((unsigned)__half_as_ushort(x[3]) << 16) | __half_as_ushort(x[2]);
    u.z = ((unsigned)__half_as_ushort(x[5]) << 16) | __half_as_ushort(x[4]);
    u.w = ((unsigned)__half_as_ushort(x[7]) << 16) | __half_as_ushort(x[6]);
    return u;
}

// ---------------- small kernels ----------------
__global__ void k_entity(const float* __restrict__ ctx, const int* __restrict__ mm,
                         const float* __restrict__ em,
                         bf16* __restrict__ oh, bf16* __restrict__ ol,
                         __half* __restrict__ of16)
{
    int bn = blockIdx.x; int b = bn / NEq, n = bn % NEq;
    __shared__ float w_s[Mq]; __shared__ int mi_s[Mq];
    if (threadIdx.x < Mq) {
        w_s[threadIdx.x]  = em[(b*NEq + n)*Mq + threadIdx.x];
        mi_s[threadIdx.x] = mm[b*Mq + threadIdx.x];
    }
    __syncthreads();
    for (int d = threadIdx.x; d < Dq; d += blockDim.x) {
        float s = 0.f;
        #pragma unroll 4
        for (int m = 0; m < Mq; m++) {
            float w = w_s[m];
            if (w != 0.f) s += w * expf(ctx[((long)b*Lq + mi_s[m])*Dq + d]);
        }
        float v = logf(s);
        bf16 h, l; split2(v, h, l);
        oh[(long)bn*Dq + d] = h; ol[(long)bn*Dq + d] = l;
        of16[(long)bn*Dq + d] = __float2half(v);
    }
}

__global__ void k_cur(const float* __restrict__ att, const int* __restrict__ mm,
                      const float* __restrict__ em, float* __restrict__ cur)
{
    int id = blockIdx.x;
    int n = id % NEq; int h = (id / NEq) % Hq; int b = id / (NEq*Hq);
    __shared__ int   act_m[Mq];
    __shared__ float act_w[Mq];
    __shared__ int   nact;
    __shared__ float invc;
    if (threadIdx.x == 0) {
        int c = 0; float cnt = 0.f;
        for (int m = 0; m < Mq; m++) {
            float w = em[(b*NEq + n)*Mq + m]; cnt += w;
            if (w != 0.f) { act_m[c] = mm[b*Mq + m]; act_w[c] = w; c++; }
        }
        nact = c; invc = 1.f / (cnt + 1e-20f);
    }
    __syncthreads();
    const float* abase = att + ((long)(b*Hq + h))*Lq*Lq;
    float* obase = cur + (long)id*Lq;
    int na = nact; float iv = invc;
    for (int l = threadIdx.x; l < Lq; l += blockDim.x) {
        float s = 0.f;
        for (int a = 0; a < na; a++) s += act_w[a] * abase[(long)act_m[a]*Lq + l];
        obase[l] = s * iv;
    }
}

__global__ void k_ca(const float* __restrict__ cur, const int* __restrict__ hts,
                     bf16* __restrict__ cah, bf16* __restrict__ cal)
{
    int bp = blockIdx.x; int b = bp / Pq, p = bp % Pq;
    int h0 = hts[p], h1 = hts[Pq + p];
    const float* c0 = cur + ((long)b*Hq*NEq + h0)*Lq;
    const float* c1 = cur + ((long)b*Hq*NEq + h1)*Lq;
    float v[4]; float local = 0.f;
    #pragma unroll
    for (int q = 0; q < 4; q++) {
        int l = threadIdx.x + q*256;
        float s = 0.f;
        #pragma unroll
        for (int h = 0; h < Hq; h++)
            s += c0[(long)h*NEq*Lq + l] * c1[(long)h*NEq*Lq + l];
        v[q] = s; local += s;
    }
    __shared__ float red[256];
    red[threadIdx.x] = local; __syncthreads();
    for (int off = 128; off > 0; off >>= 1) {
        if (threadIdx.x < off) red[threadIdx.x] += red[threadIdx.x + off];
        __syncthreads();
    }
    float inv = 1.f / (red[0] + 1e-20f);
    #pragma unroll
    for (int q = 0; q < 4; q++) {
        long o = (long)bp*Lq + threadIdx.x + q*256;
        bf16 h, l; split2(v[q]*inv, h, l);
        cah[o] = h; cal[o] = l;
    }
}

__global__ void k_split(const float* __restrict__ src, bf16* __restrict__ hi,
                        bf16* __restrict__ lo, long n)
{
    long i = (long)blockIdx.x*256 + threadIdx.x;
    if (i >= n) return;
    bf16 h, l; split2(src[i], h, l);
    hi[i] = h; lo[i] = l;
}

// batched 4-way bf16 split
struct SplitP { const float* s[4]; bf16* h[4]; bf16* l[4]; };
__global__ void k_split4(SplitP p, long n)
{
    long i = (long)blockIdx.x*256 + threadIdx.x;
    if (i >= n) return;
    int z = blockIdx.y;
    float v = p.s[z][i];
    bf16 h, l; split2(v, h, l);
    p.h[z][i] = h; p.l[z][i] = l;
}
// batched 4-way fp16 split
struct SplitPH { const float* s[4]; __half* h[4]; __half* l[4]; };
__global__ void k_split4h(SplitPH p, long n)
{
    long i = (long)blockIdx.x*256 + threadIdx.x;
    if (i >= n) return;
    int z = blockIdx.y;
    float v = p.s[z][i];
    __half h, l; split2h(v, h, l);
    p.h[z][i] = h; p.l[z][i] = l;
}

// Wrel [49152][97] -> padded fp16 split [12][4096][128]
__global__ void k_wpadsplit(const float* __restrict__ W, __half* __restrict__ Wh,
                            __half* __restrict__ Wl)
{
    long idx = (long)blockIdx.x*256 + threadIdx.x;
    int o = (int)(idx & 127);
    long row = idx >> 7;
    float v = (o < Rq) ? W[row*Rq + o] : 0.f;
    __half h, l; split2h(v, h, l);
    Wh[idx] = h; Wl[idx] = l;
}

// ---------------- mma.sync GEMM ----------------
// MODE 0: bf16 3-term, A table (opt splitout bf16+fp16).
// MODE 3: rel head fp16 2-term, A generated = fp16(outer(bh,bt)), z = head*2+ksplit.
// MODE 4: bf16 3-term + gathered fp32 Eadd.
// MODE 5: fp16 2-term, A single-fp16 table, B fp16 split, optional gathered Eadd.
struct GemmP {
    const bf16 *Ah[4], *Al[4], *Bh[4], *Bl[4];
    const float* bias[4];
    float* C[4];
    bf16 *Chi[4], *Clo[4];
    __half* Cf16[4];
    const float* Eadd[4];
    int Mz[4];
    const int* hts;
    const float *bhp, *btp;
    long sB, sC;
    int K, ldb, ldc, act, splitout;
};

template<int MODE>
__global__ __launch_bounds__(256)
void k_mma(GemmP p)
{
    __shared__ bf16 Ash[128][40], Asl[128][40];
    __shared__ bf16 Bsh[32][136],  Bsl[32][136];
    extern __shared__ float dynf[];     // MODE 3: bhF[128*68], btF[128*68]
    float* bhF = dynf;
    float* btF = dynf + 128*68;

    int z = blockIdx.z;
    const bf16 *pBh, *pBl;
    const float* pbias = 0; float* pC;
    bf16 *pChi = 0, *pClo = 0;
    __half* pCf16 = 0;
    int M;
    const bf16 *tAh = 0, *tAl = 0;
    int h3 = 0, kcb = 0;
    if (MODE == 3) {
        h3 = z >> 1;
        kcb = (z & 1) * 64;
        pBh = p.Bh[0] + (long)h3*p.sB;  pBl = p.Bl[0] + (long)h3*p.sB;
        pC  = p.C[0]  + (long)z*p.sC;
        M = p.Mz[0];
    } else {
        tAh = p.Ah[z]; tAl = p.Al[z];
        pBh = p.Bh[z]; pBl = p.Bl[z];
        pC  = p.C[z];  pbias = p.bias[z]; M = p.Mz[z];
        if (p.splitout) { pChi = p.Chi[z]; pClo = p.Clo[z]; pCf16 = p.Cf16[z]; }
    }
    int row0 = blockIdx.y * 128;
    if (row0 >= M) return;
    int col0 = blockIdx.x * 128;
    int K = p.K, ldb = p.ldb, ldc = p.ldc;
    int t = threadIdx.x;

    int arow = t >> 1;
    int ak   = (t & 1) * 16;
    int grow = row0 + arow;
    int rowc = grow < M ? grow : M - 1;
    const bf16 *srcAh0 = 0, *srcAl0 = 0;
    if (MODE != 3) {
        srcAh0 = tAh + (long)rowc*K;  srcAl0 = tAl + (long)rowc*K;
    }
    int bk = t >> 3;
    int bn = (t & 7) * 16;

    if (MODE == 3) {
        for (int idx = t; idx < 128*16; idx += 256) {
            int r = idx >> 4, q = (idx & 15) * 4;
            int rr = row0 + r; if (rr >= M) rr = M - 1;
            *(float4*)&bhF[r*68 + q] = *(const float4*)(p.bhp + (long)rr*Dq + h3*64 + q);
            *(float4*)&btF[r*68 + q] = *(const float4*)(p.btp + (long)rr*Dq + h3*64 + q);
        }
        __syncthreads();
    }

    uint4 vAh0, vAh1, vAl0, vAl1, vBh0, vBh1, vBl0, vBl1;

    #define LOAD_CHUNK(kc) do {                                                     \
        if (MODE == 3) {                                                            \
            int kk_ = (kc) + kcb;                                                   \
            int i_ = kk_ >> 1, j0_ = (kk_ & 1) * 32;                                \
            float a_ = bhF[arow*68 + i_];                                           \
            __half hh_[16];                                                         \
            _Pragma("unroll")                                                       \
            for (int q = 0; q < 16; q++)                                            \
                hh_[q] = __float2half(a_ * btF[arow*68 + j0_ + ak + q]);            \
            vAh0 = pack8h(hh_); vAh1 = pack8h(hh_ + 8);                             \
        } else {                                                                    \
            const bf16 *sh = srcAh0 + (kc)*32 + ak;                                 \
            vAh0 = *(const uint4*)sh;  vAh1 = *(const uint4*)(sh + 8);              \
            if (MODE != 5) {                                                        \
                const bf16 *sl = srcAl0 + (kc)*32 + ak;                             \
                vAl0 = *(const uint4*)sl;  vAl1 = *(const uint4*)(sl + 8);          \
            }                                                                       \
        }                                                                           \
        const bf16* bp_ = pBh + (long)(((kc) + kcb)*32 + bk)*ldb + col0 + bn;       \
        const bf16* bq_ = pBl + (long)(((kc) + kcb)*32 + bk)*ldb + col0 + bn;       \
        vBh0 = *(const uint4*)bp_;  vBh1 = *(const uint4*)(bp_ + 8);                \
        vBl0 = *(const uint4*)bq_;  vBl1 = *(const uint4*)(bq_ + 8);                \
    } while (0)

    LOAD_CHUNK(0);

    int w = t >> 5, lane = t & 31;
    int wm = (w >> 1) & 3;
    int wn = (w & 1) ^ ((w >> 2) & 1);
    float acc[2][8][4] = {};

    int KT = K >> 5;
    for (int kc = 0; kc < KT; kc++) {
        *(uint4*)&Ash[arow][ak]     = vAh0;  *(uint4*)&Ash[arow][ak + 8] = vAh1;
        if (MODE != 3 && MODE != 5) {
            *(uint4*)&Asl[arow][ak] = vAl0;  *(uint4*)&Asl[arow][ak + 8] = vAl1;
        }
        *(uint4*)&Bsh[bk][bn]       = vBh0;  *(uint4*)&Bsh[bk][bn + 8]   = vBh1;
        *(uint4*)&Bsl[bk][bn]       = vBl0;  *(uint4*)&Bsl[bk][bn + 8]   = vBl1;
        __syncthreads();
        if (kc + 1 < KT) LOAD_CHUNK(kc + 1);

        #pragma unroll
        for (int s = 0; s < 2; s++) {
            unsigned ah[2][4], al[2][4];
            int arw = wm*32 + (lane & 15);
            int acl = s*16 + (lane >> 4)*8;
            ldmx4(ah[0], su32(&Ash[arw][acl]));
            ldmx4(ah[1], su32(&Ash[arw + 16][acl]));
            if (MODE != 3 && MODE != 5) {
                ldmx4(al[0], su32(&Asl[arw][acl]));
                ldmx4(al[1], su32(&Asl[arw + 16][acl]));
            }
            int brow = s*16 + ((lane >> 3) & 1)*8 + (lane & 7);
            int bcol = wn*64 + (lane >> 4)*8;
            #pragma unroll
            for (int g = 0; g < 4; g++) {
                if (MODE == 3 && wn == 1 && g == 3) continue;
                unsigned bh_[4], bl_[4];
                ldmx4t(bh_, su32(&Bsh[brow][bcol + g*16]));
                ldmx4t(bl_, su32(&Bsl[brow][bcol + g*16]));
                #pragma unroll
                for (int mt = 0; mt < 2; mt++) {
                    if (MODE == 3) {
                        mma16816f(acc[mt][2*g],   ah[mt], bh_);
                        mma16816f(acc[mt][2*g],   ah[mt], bl_);
                        if (!(wn == 1 && g == 2)) {
                            mma16816f(acc[mt][2*g+1], ah[mt], bh_ + 2);
                            mma16816f(acc[mt][2*g+1], ah[mt], bl_ + 2);
                        }
                    } else if (MODE == 5) {
                        mma16816f(acc[mt][2*g],   ah[mt], bh_);
                        mma16816f(acc[mt][2*g],   ah[mt], bl_);
                        mma16816f(acc[mt][2*g+1], ah[mt], bh_ + 2);
                        mma16816f(acc[mt][2*g+1], ah[mt], bl_ + 2);
                    } else {
                        mma16816(acc[mt][2*g],   ah[mt], bh_);
                        mma16816(acc[mt][2*g],   ah[mt], bl_);
                        mma16816(acc[mt][2*g],   al[mt], bh_);
                        mma16816(acc[mt][2*g+1], ah[mt], bh_ + 2);
                        mma16816(acc[mt][2*g+1], ah[mt], bl_ + 2);
                        mma16816(acc[mt][2*g+1], al[mt], bh_ + 2);
                    }
                }
            }
        }
        __syncthreads();
    }
    #undef LOAD_CHUNK

    int rg = row0 + wm*32 + (lane >> 2);
    int cb = col0 + wn*64 + (lane & 3)*2;
    const float* ea[2][2] = {};
    if (MODE == 4 || (MODE == 5 && p.Eadd[z])) {
        #pragma unroll
        for (int mt = 0; mt < 2; mt++)
            #pragma unroll
            for (int hf = 0; hf < 2; hf++) {
                int rr = rg + mt*16 + hf*8;
                if (rr < M) {
                    int b = rr / Pq, pp = rr % Pq;
                    ea[mt][hf] = p.Eadd[z] + ((long)(b*NEq) + p.hts[z*Pq + pp])*Dq;
                }
            }
    }
    #pragma unroll
    for (int mt = 0; mt < 2; mt++) {
        #pragma unroll
        for (int n8 = 0; n8 < 8; n8++) {
            int rr = rg + mt*16;
            int cc = cb + n8*8;
            float v0 = acc[mt][n8][0], v1 = acc[mt][n8][1];
            float v2 = acc[mt][n8][2], v3 = acc[mt][n8][3];
            if (ea[mt][0]) { v0 += ea[mt][0][cc]; v1 += ea[mt][0][cc+1]; }
            if (ea[mt][1]) { v2 += ea[mt][1][cc]; v3 += ea[mt][1][cc+1]; }
            if (pbias) {
                float b0 = pbias[cc], b1 = pbias[cc+1];
                v0 += b0; v1 += b1; v2 += b0; v3 += b1;
            }
            if (p.act) { v0 = tanhf(v0); v1 = tanhf(v1); v2 = tanhf(v2); v3 = tanhf(v3); }
            if (rr < M) {
                *(float2*)(pC + (long)rr*ldc + cc) = make_float2(v0, v1);
                if (pChi) {
                    bf16 h0,l0,h1,l1; split2(v0,h0,l0); split2(v1,h1,l1);
                    *(__nv_bfloat162*)(pChi + (long)rr*ldc + cc) = __nv_bfloat162(h0, h1);
                    *(__nv_bfloat162*)(pClo + (long)rr*ldc + cc) = __nv_bfloat162(l0, l1);
                    *(__half2*)(pCf16 + (long)rr*ldc + cc) = __half2(__float2half(v0), __float2half(v1));
                }
            }
            if (rr + 8 < M) {
                *(float2*)(pC + (long)(rr+8)*ldc + cc) = make_float2(v2, v3);
                if (pChi) {
                    bf16 h0,l0,h1,l1; split2(v2,h0,l0); split2(v3,h1,l1);
                    *(__nv_bfloat162*)(pChi + (long)(rr+8)*ldc + cc) = __nv_bfloat162(h0, h1);
                    *(__nv_bfloat162*)(pClo + (long)(rr+8)*ldc + cc) = __nv_bfloat162(l0, l1);
                    *(__half2*)(pCf16 + (long)(rr+8)*ldc + cc) = __half2(__float2half(v2), __float2half(v3));
                }
            }
        }
    }
}

// ---------------- binary head: 16 rows per block ----------------
__global__ void k_gbl_bin16(const float* __restrict__ A, const float* __restrict__ C,
                            const float* __restrict__ W, const float* __restrict__ bias,
                            float* __restrict__ out, int* __restrict__ mask)
{
    extern __shared__ float sm[];
    float* a_s = sm;
    float* c_s = sm + 16*772;
    int n0 = blockIdx.x * 16;
    int t = threadIdx.x;
    for (int idx = t; idx < 16*192; idx += 256) {
        int r = idx / 192, q = (idx % 192) * 4;
        *(float4*)&a_s[r*772 + q] = *(const float4*)(A + (long)(n0 + r)*Dq + q);
        *(float4*)&c_s[r*772 + q] = *(const float4*)(C + (long)(n0 + r)*Dq + q);
    }
    __syncthreads();
    int nl = t & 15, grp = t >> 4;
    float s0 = 0.f, s1 = 0.f;
    for (int s = 0; s < 48; s++) {
        int hi = grp*48 + s;
        float ai = a_s[nl*772 + hi];
        const float2* w2 = (const float2*)(W + (long)hi*BSq*2);
        const float* cc = c_s + nl*772 + (hi & ~63);
        #pragma unroll 8
        for (int j = 0; j < BSq; j++) {
            float v = ai * cc[j];
            float2 ww = w2[j];
            s0 += v*ww.x; s1 += v*ww.y;
        }
    }
    __shared__ float r0[16][17], r1[16][17];
    r0[grp][nl] = s0; r1[grp][nl] = s1;
    __syncthreads();
    if (t < 16) {
        float b0 = bias[0], b1 = bias[1];
        #pragma unroll
        for (int g = 0; g < 16; g++) { b0 += r0[g][t]; b1 += r1[g][t]; }
        int n = n0 + t;
        out[n*2] = b0; out[n*2+1] = b1;
        mask[n] = (b1 > b0) ? 1 : 0;
    }
}

__global__ void k_inc(const int* __restrict__ hts, int* __restrict__ inc)
{
    if (threadIdx.x == 0 && blockIdx.x == 0) {
        int cnt[NEq];
        for (int i = 0; i < NEq; i++) cnt[i] = 0;
        for (int p = 0; p < Pq; p++) {
            int d = hts[Pq + p];
            inc[d*23 + cnt[d]++] = p;
        }
    }
}

__global__ void k_f(const float* __restrict__ Ni, const float* __restrict__ Nj,
                    const float* __restrict__ EfW, const float* __restrict__ eb,
                    const int* __restrict__ hts, float* __restrict__ f)
{
    int be = blockIdx.x; int b = be / Eq, e = be % Eq;
    int src, dst; const float* ef = 0;
    if (e < Pq) { src = hts[e]; dst = hts[Pq + e]; ef = EfW + ((long)b*Pq + e)*Dq; }
    else        { src = dst = e - Pq; }
    const float* ni = Ni + ((long)b*NEq + src)*Dq;
    const float* nj = Nj + ((long)b*NEq + dst)*Dq;
    float* o = f + (long)be*Dq;
    for (int d = threadIdx.x; d < Dq; d += blockDim.x) {
        float v = ni[d] + nj[d] + eb[d];
        if (ef) v += ef[d];
        o[d] = v;
    }
}

__global__ void k_score(const float* __restrict__ f, const float* __restrict__ attn_p,
                        const int* __restrict__ mask, float* __restrict__ score)
{
    int be = blockIdx.x; int b = be / Eq, e = be % Eq;
    int h = threadIdx.x >> 5, lane = threadIdx.x & 31;
    const float* fr = f + (long)be*Dq + h*BSq;
    float s = 0.f;
    #pragma unroll
    for (int i = lane; i < BSq; i += 32) {
        float x = fr[i];
        float lr = x > 0.f ? x : 0.2f*x;
        s += lr * attn_p[h*BSq + i];
    }
    #pragma unroll
    for (int off = 16; off; off >>= 1) s += __shfl_xor_sync(0xffffffffu, s, off);
    if (lane == 0) {
        int m = (e < Pq) ? mask[b*Pq + e] : 1;
        score[(long)be*Hq + h] = m ? s : -1e30f;
    }
}

__global__ void k_soft(const float* __restrict__ score, const int* __restrict__ inc,
                       const int* __restrict__ mask, float* __restrict__ alpha)
{
    int bn = blockIdx.x; int b = bn / NEq, n = bn % NEq;
    int h = threadIdx.x >> 5, lane = threadIdx.x & 31;
    int eid = 0; float sc = -INFINITY; float m = 0.f;
    if (lane < 24) {
        eid = (lane < 23) ? inc[n*23 + lane] : (Pq + n);
        sc  = score[((long)b*Eq + eid)*Hq + h];
        m   = (eid < Pq) ? (float)mask[b*Pq + eid] : 1.f;
    }
    float mx = sc;
    #pragma unroll
    for (int off = 16; off; off >>= 1) mx = fmaxf(mx, __shfl_xor_sync(0xffffffffu, mx, off));
    float ex = (lane < 24) ? expf(sc - mx)*m : 0.f;
    float den = ex;
    #pragma unroll
    for (int off = 16; off; off >>= 1) den += __shfl_xor_sync(0xffffffffu, den, off);
    if (lane < 24) alpha[((long)b*Eq + eid)*Hq + h] = ex / (den + 1e-20f);
}

__global__ void k_nodeout(const float* __restrict__ alpha, const float* __restrict__ Hsrc,
                          const int* __restrict__ inc, const int* __restrict__ hts,
                          __half* __restrict__ of16)
{
    int bn = blockIdx.x; int b = bn / NEq, n = bn % NEq;
    __shared__ int   esrc[24];
    __shared__ float eal[24*Hq];
    int t = threadIdx.x;
    if (t < 24) {
        int eid = (t < 23) ? inc[n*23 + t] : (Pq + n);
        esrc[t] = (t < 23) ? hts[eid] : n;
    }
    for (int t2 = t; t2 < 24*Hq; t2 += blockDim.x) {
        int slot = t2 / Hq, hh = t2 % Hq;
        int eid = (slot < 23) ? inc[n*23 + slot] : (Pq + n);
        eal[t2] = alpha[((long)b*Eq + eid)*Hq + hh];
    }
    __syncthreads();
    for (int d = t; d < Dq; d += blockDim.x) {
        int h = d >> 6;
        float s = 0.f;
        #pragma unroll
        for (int slot = 0; slot < 24; slot++)
            s += eal[slot*Hq + h] * Hsrc[((long)b*NEq + esrc[slot])*Dq + d];
        of16[(long)bn*Dq + d] = __float2half(s);
    }
}

__global__ void k_newci(const int* __restrict__ mask, const float* __restrict__ f,
                        const float* __restrict__ ci, __half* __restrict__ of16)
{
    long idx = (long)blockIdx.x*256 + threadIdx.x;
    int d = (int)(idx % Dq); long n = idx / Dq;
    int b = (int)(n / Pq), p = (int)(n % Pq);
    float v = mask[n] ? f[((long)b*Eq + p)*Dq + d] : ci[idx];
    of16[idx] = __float2half(v);
}

__global__ void k_rel_reduce(const float* __restrict__ part, const float* __restrict__ brel,
                             float* __restrict__ out)
{
    long idx = (long)blockIdx.x*256 + threadIdx.x;
    if (idx >= (long)NPq*Rq) return;
    int o = (int)(idx % Rq);
    long n = idx / Rq;
    float s = brel[o];
    #pragma unroll
    for (int h = 0; h < 24; h++) s += part[((long)h*NPq + n)*128 + o];
    out[idx] = s;
}

// ---------------- host ----------------
template <typename T>
static T* sym(const void* s) { void* p = 0; cudaGetSymbolAddress(&p, s); return (T*)p; }

extern "C" void kernel_launch(void* const* d_in, const int* in_sizes, int n_in,
                              void* d_out, int out_size)
{
    const float* ctx    = (const float*)d_in[0];
    const float* att    = (const float*)d_in[1];
    const int*   mm     = (const int*)  d_in[2];
    const float* em     = (const float*)d_in[3];
    const int*   hts    = (const int*)  d_in[4];
    const float* Whb    = (const float*)d_in[5];
    const float* bhb    = (const float*)d_in[6];
    const float* Wtb    = (const float*)d_in[7];
    const float* btb    = (const float*)d_in[8];
    const float* Wbin   = (const float*)d_in[9];
    const float* bbin   = (const float*)d_in[10];
    const float* Wrel   = (const float*)d_in[11];
    const float* brel   = (const float*)d_in[12];
    const float* Wh     = (const float*)d_in[13];
    const float* bh     = (const float*)d_in[14];
    const float* Wt     = (const float*)d_in[15];
    const float* bt     = (const float*)d_in[16];
    const float* Wnode  = (const float*)d_in[17];
    const float* Wni    = (const float*)d_in[18];
    const float* Wfij   = (const float*)d_in[19];
    const float* Wnj    = (const float*)d_in[20];
    const float* attn_p = (const float*)d_in[21];
    const float* egat_b = (const float*)d_in[22];

    float* outBin = (float*)d_out;
    float* outRel = outBin + (long)NPq*2;

    float* p_cur   = sym<float>(g_cur);
    float* p_ci    = sym<float>(g_ci);
    float* p_bh    = sym<float>(g_bh);
    float* p_bt    = sym<float>(g_bt);
    int*   p_mask  = sym<int>(g_mask);
    float* p_Ni    = sym<float>(g_Ni);
    float* p_Nj    = sym<float>(g_Nj);
    float* p_Hs    = sym<float>(g_Hs);
    float* p_EfW   = sym<float>(g_EfW);
    float* p_f     = sym<float>(g_f);
    float* p_score = sym<float>(g_score);
    float* p_alpha = sym<float>(g_alpha);
    float* p_rpart = sym<float>(g_relpart);
    int*   p_inc   = sym<int>(g_inc);
    float* p_Ebh   = sym<float>(g_Ebh);
    float* p_Ebt   = sym<float>(g_Ebt);
    float* p_Erh   = sym<float>(g_Erh);
    float* p_Ert   = sym<float>(g_Ert);

    bf16 *enth = sym<bf16>(g_enth), *entl = sym<bf16>(g_entl);
    bf16 *cah  = sym<bf16>(g_cah),  *cal  = sym<bf16>(g_cal);
    bf16 *cih  = sym<bf16>(g_cih),  *cil  = sym<bf16>(g_cil);
    bf16 *ctxh = sym<bf16>(g_ctxh), *ctxl = sym<bf16>(g_ctxl);
    bf16 *Whbh = sym<bf16>(g_Whbh), *Whbl = sym<bf16>(g_Whbl);
    bf16 *Wtbh = sym<bf16>(g_Wtbh), *Wtbl = sym<bf16>(g_Wtbl);
    __half *cif16  = sym<__half>(g_cif16);
    __half *entf16 = sym<__half>(g_entf16);
    __half *nchf16 = sym<__half>(g_nchf16);
    __half *noutf16= sym<__half>(g_noutf16);
    __half *Whh  = sym<__half>(g_Whh),  *Whl  = sym<__half>(g_Whl);
    __half *Wth  = sym<__half>(g_Wth),  *Wtl  = sym<__half>(g_Wtl);
    __half *Wfijh= sym<__half>(g_Wfijh),*Wfijl= sym<__half>(g_Wfijl);
    __half *Wnih = sym<__half>(g_Wnih), *Wnil = sym<__half>(g_Wnil);
    __half *Wnjh = sym<__half>(g_Wnjh), *Wnjl = sym<__half>(g_Wnjl);
    __half *Wnodeh=sym<__half>(g_Wnodeh),*Wnodel=sym<__half>(g_Wnodel);
    __half *Wpadh = sym<__half>(g_Wpadh), *Wpadl = sym<__half>(g_Wpadl);

    cudaFuncSetAttribute(k_mma<3>, cudaFuncAttributeMaxDynamicSharedMemorySize, 2*128*68*4);
    cudaFuncSetAttribute(k_gbl_bin16, cudaFuncAttributeMaxDynamicSharedMemorySize, 2*16*772*4);

    // ---- pooling + conversions ----
    k_entity<<<Bq*NEq, 256>>>(ctx, mm, em, enth, entl, entf16);
    k_cur<<<Bq*Hq*NEq, 256>>>(att, mm, em, p_cur);
    k_ca<<<Bq*Pq, 256>>>(p_cur, hts, cah, cal);
    k_split<<<(int)(((long)Bq*Lq*Dq + 255)/256), 256>>>(ctx, ctxh, ctxl, (long)Bq*Lq*Dq);
    {
        SplitP sp = {};
        sp.s[0] = Whb; sp.h[0] = Whbh; sp.l[0] = Whbl;
        sp.s[1] = Wtb; sp.h[1] = Wtbh; sp.l[1] = Wtbl;
        k_split4<<<dim3((2*Dq*Dq + 255)/256, 2), 256>>>(sp, (long)2*Dq*Dq);
    }
    {
        SplitPH sp = {};
        sp.s[0] = Wh; sp.h[0] = Whh; sp.l[0] = Whl;
        sp.s[1] = Wt; sp.h[1] = Wth; sp.l[1] = Wtl;
        k_split4h<<<dim3((2*Dq*Dq + 255)/256, 2), 256>>>(sp, (long)2*Dq*Dq);
    }
    {
        SplitPH sp = {};
        sp.s[0] = Wfij;  sp.h[0] = Wfijh;  sp.l[0] = Wfijl;
        sp.s[1] = Wni;   sp.h[1] = Wnih;   sp.l[1] = Wnil;
        sp.s[2] = Wnj;   sp.h[2] = Wnjh;   sp.l[2] = Wnjl;
        sp.s[3] = Wnode; sp.h[3] = Wnodeh; sp.l[3] = Wnodel;
        k_split4h<<<dim3((Dq*Dq + 255)/256, 4), 256>>>(sp, (long)Dq*Dq);
    }
    k_wpadsplit<<<(int)(((long)Hq*4096*128)/256), 256>>>(Wrel, Wpadh, Wpadl);
    k_inc<<<1, 32>>>(hts, p_inc);

    // ---- ci = ca @ ctx (batched over B), splitout: fp32 + bf16 h/l + fp16 ----
    {
        GemmP g = {};
        for (int z = 0; z < Bq; z++) {
            g.Ah[z] = cah + (long)z*Pq*Lq;  g.Al[z] = cal + (long)z*Pq*Lq;
            g.Bh[z] = ctxh + (long)z*Lq*Dq; g.Bl[z] = ctxl + (long)z*Lq*Dq;
            g.C[z]  = p_ci + (long)z*Pq*Dq;
            g.Chi[z]= cih  + (long)z*Pq*Dq; g.Clo[z]= cil + (long)z*Pq*Dq;
            g.Cf16[z] = cif16 + (long)z*Pq*Dq;
            g.Mz[z] = Pq;
        }
        g.K = Lq; g.ldb = Dq; g.ldc = Dq; g.splitout = 1;
        k_mma<0><<<dim3(6, 5, 4), 256>>>(g);
    }

    // ---- Ebin = ent96 @ W_top (bf16 3-term; mask chain) ----
    {
        GemmP g = {};
        g.Ah[0] = enth; g.Al[0] = entl; g.Bh[0] = Whbh; g.Bl[0] = Whbl; g.C[0] = p_Ebh; g.Mz[0] = Bq*NEq;
        g.Ah[1] = enth; g.Al[1] = entl; g.Bh[1] = Wtbh; g.Bl[1] = Wtbl; g.C[1] = p_Ebt; g.Mz[1] = Bq*NEq;
        g.K = Dq; g.ldb = Dq; g.ldc = Dq;
        k_mma<0><<<dim3(6, 1, 2), 256>>>(g);
    }

    // ---- bin pair (bf16 3-term; mask chain) ----
    {
        GemmP g = {};
        g.Ah[0] = cih; g.Al[0] = cil; g.Bh[0] = Whbh + (long)Dq*Dq; g.Bl[0] = Whbl + (long)Dq*Dq;
        g.bias[0] = bhb; g.C[0] = p_bh; g.Eadd[0] = p_Ebh; g.Mz[0] = NPq;
        g.Ah[1] = cih; g.Al[1] = cil; g.Bh[1] = Wtbh + (long)Dq*Dq; g.Bl[1] = Wtbl + (long)Dq*Dq;
        g.bias[1] = btb; g.C[1] = p_bt; g.Eadd[1] = p_Ebt; g.Mz[1] = NPq;
        g.hts = hts; g.K = Dq; g.ldb = Dq; g.ldc = Dq; g.act = 1;
        k_mma<4><<<dim3(6, 18, 2), 256>>>(g);
    }
    k_gbl_bin16<<<NPq/16, 256, 2*16*772*4>>>(p_bh, p_bt, Wbin, bbin, outBin, p_mask);

    // ---- EGAT linear layers (fp16 2-term) ----
    {
        GemmP g = {};
        g.Ah[0] = (const bf16*)cif16;  g.Bh[0] = (const bf16*)Wfijh;  g.Bl[0] = (const bf16*)Wfijl;  g.C[0] = p_EfW; g.Mz[0] = NPq;
        g.Ah[1] = (const bf16*)entf16; g.Bh[1] = (const bf16*)Wnih;   g.Bl[1] = (const bf16*)Wnil;   g.C[1] = p_Ni;  g.Mz[1] = Bq*NEq;
        g.Ah[2] = (const bf16*)entf16; g.Bh[2] = (const bf16*)Wnjh;   g.Bl[2] = (const bf16*)Wnjl;   g.C[2] = p_Nj;  g.Mz[2] = Bq*NEq;
        g.Ah[3] = (const bf16*)entf16; g.Bh[3] = (const bf16*)Wnodeh; g.Bl[3] = (const bf16*)Wnodel; g.C[3] = p_Hs;  g.Mz[3] = Bq*NEq;
        g.K = Dq; g.ldb = Dq; g.ldc = Dq;
        k_mma<5><<<dim3(6, 18, 4), 256>>>(g);
    }
    k_f<<<Bq*Eq, 256>>>(p_Ni, p_Nj, p_EfW, egat_b, hts, p_f);
    k_score<<<Bq*Eq, 384>>>(p_f, attn_p, p_mask, p_score);
    k_soft<<<Bq*NEq, 384>>>(p_score, p_inc, p_mask, p_alpha);
    k_nodeout<<<Bq*NEq, 256>>>(p_alpha, p_Hs, p_inc, hts, noutf16);

    // ---- relation head ----
    k_newci<<<NPq*Dq/256, 256>>>(p_mask, p_f, p_ci, nchf16);
    // Er = nout96 @ W_top (fp16 2-term)
    {
        GemmP g = {};
        g.Ah[0] = (const bf16*)noutf16; g.Bh[0] = (const bf16*)Whh; g.Bl[0] = (const bf16*)Whl; g.C[0] = p_Erh; g.Mz[0] = Bq*NEq;
        g.Ah[1] = (const bf16*)noutf16; g.Bh[1] = (const bf16*)Wth; g.Bl[1] = (const bf16*)Wtl; g.C[1] = p_Ert; g.Mz[1] = Bq*NEq;
        g.K = Dq; g.ldb = Dq; g.ldc = Dq;
        k_mma<5><<<dim3(6, 1, 2), 256>>>(g);
    }
    // rel pair: tanh(nch @ W_bot + Er[ent] + bias) (fp16 2-term)
    {
        GemmP g = {};
        g.Ah[0] = (const bf16*)nchf16; g.Bh[0] = (const bf16*)(Whh + (long)Dq*Dq); g.Bl[0] = (const bf16*)(Whl + (long)Dq*Dq);
        g.bias[0] = bh; g.C[0] = p_bh; g.Eadd[0] = p_Erh; g.Mz[0] = NPq;
        g.Ah[1] = (const bf16*)nchf16; g.Bh[1] = (const bf16*)(Wth + (long)Dq*Dq); g.Bl[1] = (const bf16*)(Wtl + (long)Dq*Dq);
        g.bias[1] = bt; g.C[1] = p_bt; g.Eadd[1] = p_Ert; g.Mz[1] = NPq;
        g.hts = hts; g.K = Dq; g.ldb = Dq; g.ldc = Dq; g.act = 1;
        k_mma<5><<<dim3(6, 18, 2), 256>>>(g);
    }
    // rel head: 24 = 12 heads x 2 K-splits; fp16 2-term
    {
        GemmP g = {};
        g.Bh[0] = (const bf16*)Wpadh; g.Bl[0] = (const bf16*)Wpadl;
        g.C[0] = p_rpart; g.Mz[0] = NPq;
        g.bhp = p_bh; g.btp = p_bt;
        g.sB = (long)4096*128; g.sC = (long)NPq*128;
        g.K = 2048; g.ldb = 128; g.ldc = 128;
        k_mma<3><<<dim3(1, 18, 24), 256, 2*128*68*4>>>(g);
    }
    k_rel_reduce<<<((long)NPq*Rq + 255)/256, 256>>>(p_rpart, brel, outRel);
}